// round 1
// baseline (speedup 1.0000x reference)
#include <cuda_runtime.h>
#include <cuda_bf16.h>
#include <cstdint>

// Problem constants
#define BATCH    2
#define T_SEQ    2048
#define D_MODEL  1024
#define N_HEADS  16
#define HD       64
#define BT       (BATCH * T_SEQ)     // 4096 rows
#define QKV_N    (3 * D_MODEL)       // 3072
#define BIAS_COEF 0.1f

// Scratch (device globals: allocation-free per harness rules)
__device__ float g_qkv[(size_t)BT * QKV_N];   // [4096, 3072]
__device__ float g_att[(size_t)BT * D_MODEL]; // [4096, 1024]

// ---------------------------------------------------------------------------
// Classic 128x128 register-blocked SGEMM with bias: C = A[MxK] @ B[KxN] + bias
// 256 threads, each computes 8x8. Requires M%128==0, N%128==0, K%8==0.
// ---------------------------------------------------------------------------
__global__ __launch_bounds__(256) void sgemm_bias_kernel(
    const float* __restrict__ A, const float* __restrict__ B,
    const float* __restrict__ bias, float* __restrict__ C,
    int M, int N, int K)
{
    const int BM = 128, BN = 128, BK = 8, TM = 8, TN = 8;
    __shared__ float As[BK][BM];
    __shared__ float Bs[BK][BN];

    int bx = blockIdx.x;            // along N
    int by = blockIdx.y;            // along M
    int tid = threadIdx.x;
    int tx = tid % (BN / TN);       // 0..15
    int ty = tid / (BN / TN);       // 0..15

    float acc[TM][TN];
#pragma unroll
    for (int i = 0; i < TM; i++)
#pragma unroll
        for (int j = 0; j < TN; j++) acc[i][j] = 0.0f;

    // Load mapping
    int aRow = tid / 2;             // 0..127
    int aCol = (tid % 2) * 4;       // 0 or 4
    int bRow = tid / 32;            // 0..7
    int bCol = (tid % 32) * 4;      // 0..124

    const float* Aptr = A + (size_t)(by * BM) * K;
    const float* Bptr = B + bx * BN;

    for (int k0 = 0; k0 < K; k0 += BK) {
        float4 a = *(const float4*)&Aptr[(size_t)aRow * K + k0 + aCol];
        As[aCol + 0][aRow] = a.x;
        As[aCol + 1][aRow] = a.y;
        As[aCol + 2][aRow] = a.z;
        As[aCol + 3][aRow] = a.w;
        *(float4*)&Bs[bRow][bCol] = *(const float4*)&Bptr[(size_t)(k0 + bRow) * N + bCol];
        __syncthreads();

#pragma unroll
        for (int kk = 0; kk < BK; kk++) {
            float ar[TM], br[TN];
#pragma unroll
            for (int i = 0; i < TM; i++) ar[i] = As[kk][ty * TM + i];
#pragma unroll
            for (int j = 0; j < TN; j++) br[j] = Bs[kk][tx * TN + j];
#pragma unroll
            for (int i = 0; i < TM; i++)
#pragma unroll
                for (int j = 0; j < TN; j++) acc[i][j] = fmaf(ar[i], br[j], acc[i][j]);
        }
        __syncthreads();
    }

    // Epilogue: bias + store
    float bcol[TN];
#pragma unroll
    for (int j = 0; j < TN; j += 4) {
        float4 bb = *(const float4*)&bias[bx * BN + tx * TN + j];
        bcol[j] = bb.x; bcol[j + 1] = bb.y; bcol[j + 2] = bb.z; bcol[j + 3] = bb.w;
    }
#pragma unroll
    for (int i = 0; i < TM; i++) {
        size_t row = (size_t)(by * BM + ty * TM + i);
#pragma unroll
        for (int j = 0; j < TN; j += 4) {
            float4 v;
            v.x = acc[i][j + 0] + bcol[j + 0];
            v.y = acc[i][j + 1] + bcol[j + 1];
            v.z = acc[i][j + 2] + bcol[j + 2];
            v.w = acc[i][j + 3] + bcol[j + 3];
            *(float4*)&C[row * N + bx * BN + tx * TN + j] = v;
        }
    }
}

// ---------------------------------------------------------------------------
// Flash-attention style streaming attention (fp32).
// Grid: (T/128, H, B). 128 threads; each thread owns one query row.
// qkv layout: [BT, 3072] with Q at col h*64, K at 1024+h*64, V at 2048+h*64.
// Online softmax with additive per-key boundary bias. Output -> g_att [BT, D].
// ---------------------------------------------------------------------------
#define KT 32          // key-tile rows
#define QROWS 128

__global__ __launch_bounds__(QROWS) void attn_kernel(
    const float* __restrict__ qkv, const float* __restrict__ bscore,
    float* __restrict__ att)
{
    const int tid = threadIdx.x;
    const int h = blockIdx.y;
    const int b = blockIdx.z;
    const int tq = blockIdx.x * QROWS + tid;
    const float scale = 0.125f;   // hd^-0.5 = 1/8

    __shared__ float Ks[KT][HD];
    __shared__ float Vs[KT][HD];
    __shared__ float bs[KT];

    float q[HD], o[HD];
    const float* qrow = qkv + (size_t)(b * T_SEQ + tq) * QKV_N + h * HD;
#pragma unroll
    for (int d = 0; d < HD; d += 4) {
        float4 t = *(const float4*)(qrow + d);
        q[d + 0] = t.x * scale; q[d + 1] = t.y * scale;
        q[d + 2] = t.z * scale; q[d + 3] = t.w * scale;
    }
#pragma unroll
    for (int d = 0; d < HD; d++) o[d] = 0.0f;
    float m = -1e30f, l = 0.0f;

    for (int kt = 0; kt < T_SEQ / KT; kt++) {
        const float* kbase = qkv + (size_t)(b * T_SEQ + kt * KT) * QKV_N + D_MODEL + h * HD;
        const float* vbase = kbase + D_MODEL;
        // KT*HD = 2048 floats = 512 float4 per buffer; 128 threads -> 4 each
#pragma unroll
        for (int i = 0; i < 4; i++) {
            int idx = tid + i * 128;
            int row = idx >> 4;            // HD/4 = 16 float4 per row
            int col = (idx & 15) << 2;
            *(float4*)&Ks[row][col] = *(const float4*)(kbase + (size_t)row * QKV_N + col);
            *(float4*)&Vs[row][col] = *(const float4*)(vbase + (size_t)row * QKV_N + col);
        }
        if (tid < KT) bs[tid] = bscore[b * T_SEQ + kt * KT + tid] * BIAS_COEF;
        __syncthreads();

        float s[KT];
        float mt = -1e30f;
#pragma unroll
        for (int j = 0; j < KT; j++) {
            float acc = 0.0f;
#pragma unroll
            for (int d = 0; d < HD; d += 4) {
                float4 kv = *(const float4*)&Ks[j][d];
                acc = fmaf(q[d + 0], kv.x, acc);
                acc = fmaf(q[d + 1], kv.y, acc);
                acc = fmaf(q[d + 2], kv.z, acc);
                acc = fmaf(q[d + 3], kv.w, acc);
            }
            acc += bs[j];
            s[j] = acc;
            mt = fmaxf(mt, acc);
        }
        float mnew = fmaxf(m, mt);
        float c = __expf(m - mnew);
        l *= c;
#pragma unroll
        for (int d = 0; d < HD; d++) o[d] *= c;
#pragma unroll
        for (int j = 0; j < KT; j++) {
            float p = __expf(s[j] - mnew);
            l += p;
#pragma unroll
            for (int d = 0; d < HD; d += 4) {
                float4 vv = *(const float4*)&Vs[j][d];
                o[d + 0] = fmaf(p, vv.x, o[d + 0]);
                o[d + 1] = fmaf(p, vv.y, o[d + 1]);
                o[d + 2] = fmaf(p, vv.z, o[d + 2]);
                o[d + 3] = fmaf(p, vv.w, o[d + 3]);
            }
        }
        m = mnew;
        __syncthreads();
    }

    float inv = 1.0f / l;
    float* orow = att + (size_t)(b * T_SEQ + tq) * D_MODEL + h * HD;
#pragma unroll
    for (int d = 0; d < HD; d += 4) {
        float4 t;
        t.x = o[d + 0] * inv; t.y = o[d + 1] * inv;
        t.z = o[d + 2] * inv; t.w = o[d + 3] * inv;
        *(float4*)(orow + d) = t;
    }
}

// ---------------------------------------------------------------------------
// Launch
// ---------------------------------------------------------------------------
extern "C" void kernel_launch(void* const* d_in, const int* in_sizes, int n_in,
                              void* d_out, int out_size)
{
    const float* x      = (const float*)d_in[0];  // [2,2048,1024]
    const float* bscore = (const float*)d_in[1];  // [2,2048]
    const float* W_qkv  = (const float*)d_in[2];  // [1024,3072]
    const float* b_qkv  = (const float*)d_in[3];  // [3072]
    const float* W_out  = (const float*)d_in[4];  // [1024,1024]
    const float* b_out  = (const float*)d_in[5];  // [1024]
    float* out = (float*)d_out;                   // [2,2048,1024]

    float* qkv_ptr = nullptr;
    float* att_ptr = nullptr;
    cudaGetSymbolAddress((void**)&qkv_ptr, g_qkv);
    cudaGetSymbolAddress((void**)&att_ptr, g_att);

    // 1) QKV projection: [4096,1024] @ [1024,3072] + b
    sgemm_bias_kernel<<<dim3(QKV_N / 128, BT / 128), 256>>>(
        x, W_qkv, b_qkv, qkv_ptr, BT, QKV_N, D_MODEL);

    // 2) Attention (flash streaming)
    attn_kernel<<<dim3(T_SEQ / QROWS, N_HEADS, BATCH), QROWS>>>(
        qkv_ptr, bscore, att_ptr);

    // 3) Output projection: [4096,1024] @ [1024,1024] + b
    sgemm_bias_kernel<<<dim3(D_MODEL / 128, BT / 128), 256>>>(
        att_ptr, W_out, b_out, out, BT, D_MODEL, D_MODEL);
}

// round 3
// speedup vs baseline: 3.3146x; 3.3146x over previous
#include <cuda_runtime.h>
#include <cuda_bf16.h>
#include <cstdint>

#define BATCH    2
#define T_SEQ    2048
#define D_MODEL  1024
#define N_HEADS  16
#define HD       64
#define BT       (BATCH * T_SEQ)     // 4096
#define QKV_N    (3 * D_MODEL)       // 3072
#define BIAS_COEF 0.1f

// Scratch (device globals: allocation-free per harness rules)
__device__ float g_qkv[(size_t)BT * QKV_N];   // [4096, 3072]
__device__ float g_att[(size_t)BT * D_MODEL]; // [4096, 1024]

// ---------------------------------------------------------------------------
// tf32 helpers
// ---------------------------------------------------------------------------
__device__ __forceinline__ uint32_t f2tf32(float f) {
    uint32_t r;
    asm("cvt.rna.tf32.f32 %0, %1;" : "=r"(r) : "f"(f));
    return r;
}

__device__ __forceinline__ void mma_tf32(float c[4],
    uint32_t a0, uint32_t a1, uint32_t a2, uint32_t a3,
    uint32_t b0, uint32_t b1)
{
    asm volatile(
        "mma.sync.aligned.m16n8k8.row.col.f32.tf32.tf32.f32 "
        "{%0,%1,%2,%3}, {%4,%5,%6,%7}, {%8,%9}, {%0,%1,%2,%3};"
        : "+f"(c[0]), "+f"(c[1]), "+f"(c[2]), "+f"(c[3])
        : "r"(a0), "r"(a1), "r"(a2), "r"(a3), "r"(b0), "r"(b1));
}

// ---------------------------------------------------------------------------
// TF32 tensor-core GEMM with bias: C = A[MxK] @ B[KxN] + bias
// Block 128x128, BK=32, 8 warps (2x4), warp tile 64x32 (4x4 m16n8 tiles).
// Requires M%128==0, N%128==0, K%32==0.
// ---------------------------------------------------------------------------
__global__ __launch_bounds__(256) void gemm_tf32_bias(
    const float* __restrict__ A, const float* __restrict__ B,
    const float* __restrict__ bias, float* __restrict__ C,
    int M, int N, int K)
{
    __shared__ uint32_t As[128 * 36];   // [row][k], stride 36 (pad 4)
    __shared__ uint32_t Bs[32 * 132];   // [k][col], stride 132 (pad 4)

    const int tid  = threadIdx.x;
    const int lane = tid & 31;
    const int warp = tid >> 5;
    const int wr = warp >> 2;           // 0..1
    const int wc = warp & 3;            // 0..3
    const int g = lane >> 2;            // groupID 0..7
    const int t = lane & 3;             // threadID in group 0..3
    const int bx = blockIdx.x, by = blockIdx.y;

    float acc[4][4][4];
#pragma unroll
    for (int mt = 0; mt < 4; mt++)
#pragma unroll
        for (int nt = 0; nt < 4; nt++)
#pragma unroll
            for (int i = 0; i < 4; i++) acc[mt][nt][i] = 0.0f;

    const float* Ag = A + (size_t)(by * 128) * K;
    const float* Bg = B + bx * 128;

    for (int k0 = 0; k0 < K; k0 += 32) {
        // Load A tile: 128x32 = 1024 float4s, 4 per thread
#pragma unroll
        for (int j = 0; j < 4; j++) {
            int i = tid + 256 * j;
            int row = i >> 3, c4 = (i & 7) << 2;
            float4 v = *(const float4*)(Ag + (size_t)row * K + k0 + c4);
            uint32_t* d = &As[row * 36 + c4];
            d[0] = f2tf32(v.x); d[1] = f2tf32(v.y);
            d[2] = f2tf32(v.z); d[3] = f2tf32(v.w);
        }
        // Load B tile: 32x128 = 1024 float4s
#pragma unroll
        for (int j = 0; j < 4; j++) {
            int i = tid + 256 * j;
            int row = i >> 5, c4 = (i & 31) << 2;
            float4 v = *(const float4*)(Bg + (size_t)(k0 + row) * N + c4);
            uint32_t* d = &Bs[row * 132 + c4];
            d[0] = f2tf32(v.x); d[1] = f2tf32(v.y);
            d[2] = f2tf32(v.z); d[3] = f2tf32(v.w);
        }
        __syncthreads();

#pragma unroll
        for (int kk = 0; kk < 4; kk++) {
            uint32_t a[4][4], bf[4][2];
#pragma unroll
            for (int mt = 0; mt < 4; mt++) {
                int r = wr * 64 + mt * 16 + g;
                int c = kk * 8 + t;
                a[mt][0] = As[r * 36 + c];
                a[mt][1] = As[(r + 8) * 36 + c];
                a[mt][2] = As[r * 36 + c + 4];
                a[mt][3] = As[(r + 8) * 36 + c + 4];
            }
#pragma unroll
            for (int nt = 0; nt < 4; nt++) {
                int c = wc * 32 + nt * 8 + g;
                int r = kk * 8 + t;
                bf[nt][0] = Bs[r * 132 + c];
                bf[nt][1] = Bs[(r + 4) * 132 + c];
            }
#pragma unroll
            for (int mt = 0; mt < 4; mt++)
#pragma unroll
                for (int nt = 0; nt < 4; nt++)
                    mma_tf32(acc[mt][nt], a[mt][0], a[mt][1], a[mt][2], a[mt][3],
                             bf[nt][0], bf[nt][1]);
        }
        __syncthreads();
    }

    // Epilogue: bias + store (float2)
#pragma unroll
    for (int mt = 0; mt < 4; mt++) {
#pragma unroll
        for (int nt = 0; nt < 4; nt++) {
            int row = by * 128 + wr * 64 + mt * 16 + g;
            int col = bx * 128 + wc * 32 + nt * 8 + 2 * t;
            float b0 = bias[col], b1 = bias[col + 1];
            float2 v0 = make_float2(acc[mt][nt][0] + b0, acc[mt][nt][1] + b1);
            float2 v1 = make_float2(acc[mt][nt][2] + b0, acc[mt][nt][3] + b1);
            *(float2*)&C[(size_t)row * N + col] = v0;
            *(float2*)&C[(size_t)(row + 8) * N + col] = v1;
        }
    }
}

// ---------------------------------------------------------------------------
// Flash attention with tf32 tensor cores.
// Grid: (T/64, H, B), 128 threads (4 warps). Warp w owns query rows 16w..16w+15.
// 64-key tiles: S = Q K^T via MMA, register online softmax, P via smem (warp-
// private rows), PV via MMA.
// ---------------------------------------------------------------------------
#define ATTN_SMEM_U32 (3 * 64 * 68 + 64)
#define ATTN_SMEM_BYTES (ATTN_SMEM_U32 * 4)

__global__ __launch_bounds__(128) void attn_tf32(
    const float* __restrict__ qkv, const float* __restrict__ bscore,
    float* __restrict__ att)
{
    extern __shared__ uint32_t sm[];
    uint32_t* Ks = sm;                     // [64 key][68], tf32 bits
    uint32_t* Vs = sm + 64 * 68;           // [64 key][68]
    uint32_t* Ps = sm + 2 * 64 * 68;       // [64 q][68]
    float* bias_s = (float*)(sm + 3 * 64 * 68);  // [64]

    const int tid  = threadIdx.x;
    const int lane = tid & 31;
    const int w = tid >> 5;
    const int g = lane >> 2;
    const int t = lane & 3;
    const int qt = blockIdx.x, h = blockIdx.y, b = blockIdx.z;

    // Preload Q fragments (rows w*16+g and +8), scale folded in
    uint32_t qa[8][4];
    {
        const float* q0 = qkv + (size_t)(b * T_SEQ + qt * 64 + w * 16 + g) * QKV_N + h * HD;
        const float* q8 = q0 + 8 * (size_t)QKV_N;
#pragma unroll
        for (int ks = 0; ks < 8; ks++) {
            int c = ks * 8 + t;
            qa[ks][0] = f2tf32(q0[c] * 0.125f);
            qa[ks][1] = f2tf32(q8[c] * 0.125f);
            qa[ks][2] = f2tf32(q0[c + 4] * 0.125f);
            qa[ks][3] = f2tf32(q8[c + 4] * 0.125f);
        }
    }

    float oacc[8][4];
#pragma unroll
    for (int nt = 0; nt < 8; nt++)
#pragma unroll
        for (int i = 0; i < 4; i++) oacc[nt][i] = 0.0f;
    float m0 = -1e30f, m1 = -1e30f, l0 = 0.0f, l1 = 0.0f;

    const int prow = w * 16 + g;   // this thread's P/Q row (and +8)

    for (int kt = 0; kt < T_SEQ / 64; kt++) {
        const float* kb = qkv + (size_t)(b * T_SEQ + kt * 64) * QKV_N + D_MODEL + h * HD;
        const float* vb = kb + D_MODEL;
        // Load K,V tiles: 64x64 each = 1024 float4 per tile, 8 per thread
#pragma unroll
        for (int j = 0; j < 8; j++) {
            int i = tid + 128 * j;
            int row = i >> 4, c4 = (i & 15) << 2;
            float4 kv4 = *(const float4*)(kb + (size_t)row * QKV_N + c4);
            uint32_t* dk = &Ks[row * 68 + c4];
            dk[0] = f2tf32(kv4.x); dk[1] = f2tf32(kv4.y);
            dk[2] = f2tf32(kv4.z); dk[3] = f2tf32(kv4.w);
            float4 vv4 = *(const float4*)(vb + (size_t)row * QKV_N + c4);
            uint32_t* dv = &Vs[row * 68 + c4];
            dv[0] = f2tf32(vv4.x); dv[1] = f2tf32(vv4.y);
            dv[2] = f2tf32(vv4.z); dv[3] = f2tf32(vv4.w);
        }
        if (tid < 64) bias_s[tid] = bscore[b * T_SEQ + kt * 64 + tid] * BIAS_COEF;
        __syncthreads();

        // S = Q K^T  (warp computes 16x64)
        float sacc[8][4];
#pragma unroll
        for (int nt = 0; nt < 8; nt++)
#pragma unroll
            for (int i = 0; i < 4; i++) sacc[nt][i] = 0.0f;
#pragma unroll
        for (int ks = 0; ks < 8; ks++) {
#pragma unroll
            for (int nt = 0; nt < 8; nt++) {
                int key = nt * 8 + g;
                int d = ks * 8 + t;
                uint32_t b0 = Ks[key * 68 + d];
                uint32_t b1 = Ks[key * 68 + d + 4];
                mma_tf32(sacc[nt], qa[ks][0], qa[ks][1], qa[ks][2], qa[ks][3], b0, b1);
            }
        }

        // bias add + tile max
        float mt0 = -1e30f, mt1 = -1e30f;
#pragma unroll
        for (int nt = 0; nt < 8; nt++) {
            float bb0 = bias_s[nt * 8 + 2 * t];
            float bb1 = bias_s[nt * 8 + 2 * t + 1];
            sacc[nt][0] += bb0; sacc[nt][1] += bb1;
            sacc[nt][2] += bb0; sacc[nt][3] += bb1;
            mt0 = fmaxf(mt0, fmaxf(sacc[nt][0], sacc[nt][1]));
            mt1 = fmaxf(mt1, fmaxf(sacc[nt][2], sacc[nt][3]));
        }
        mt0 = fmaxf(mt0, __shfl_xor_sync(0xFFFFFFFFu, mt0, 1));
        mt0 = fmaxf(mt0, __shfl_xor_sync(0xFFFFFFFFu, mt0, 2));
        mt1 = fmaxf(mt1, __shfl_xor_sync(0xFFFFFFFFu, mt1, 1));
        mt1 = fmaxf(mt1, __shfl_xor_sync(0xFFFFFFFFu, mt1, 2));

        float mn0 = fmaxf(m0, mt0), mn1 = fmaxf(m1, mt1);
        float c0 = __expf(m0 - mn0), c1 = __expf(m1 - mn1);
        m0 = mn0; m1 = mn1;

        float ls0 = 0.0f, ls1 = 0.0f;
#pragma unroll
        for (int nt = 0; nt < 8; nt++) {
            float p0 = __expf(sacc[nt][0] - mn0);
            float p1 = __expf(sacc[nt][1] - mn0);
            float p2 = __expf(sacc[nt][2] - mn1);
            float p3 = __expf(sacc[nt][3] - mn1);
            ls0 += p0 + p1; ls1 += p2 + p3;
            int col = nt * 8 + 2 * t;
            Ps[prow * 68 + col] = f2tf32(p0);
            Ps[prow * 68 + col + 1] = f2tf32(p1);
            Ps[(prow + 8) * 68 + col] = f2tf32(p2);
            Ps[(prow + 8) * 68 + col + 1] = f2tf32(p3);
            oacc[nt][0] *= c0; oacc[nt][1] *= c0;
            oacc[nt][2] *= c1; oacc[nt][3] *= c1;
        }
        ls0 += __shfl_xor_sync(0xFFFFFFFFu, ls0, 1);
        ls0 += __shfl_xor_sync(0xFFFFFFFFu, ls0, 2);
        ls1 += __shfl_xor_sync(0xFFFFFFFFu, ls1, 1);
        ls1 += __shfl_xor_sync(0xFFFFFFFFu, ls1, 2);
        l0 = l0 * c0 + ls0;
        l1 = l1 * c1 + ls1;
        __syncwarp(0xFFFFFFFFu);   // P rows are warp-private; warp-level visibility

        // O += P V  (warp's 16 rows x 64 d)
#pragma unroll
        for (int ks = 0; ks < 8; ks++) {
            int c = ks * 8 + t;
            uint32_t pa0 = Ps[prow * 68 + c];
            uint32_t pa1 = Ps[(prow + 8) * 68 + c];
            uint32_t pa2 = Ps[prow * 68 + c + 4];
            uint32_t pa3 = Ps[(prow + 8) * 68 + c + 4];
#pragma unroll
            for (int nt = 0; nt < 8; nt++) {
                int d = nt * 8 + g;
                int key = ks * 8 + t;
                uint32_t b0 = Vs[key * 68 + d];
                uint32_t b1 = Vs[(key + 4) * 68 + d];
                mma_tf32(oacc[nt], pa0, pa1, pa2, pa3, b0, b1);
            }
        }
        __syncthreads();   // protect K/V (and bias) before next tile load
    }

    // Normalize + store
    float inv0 = 1.0f / l0, inv1 = 1.0f / l1;
    int row = b * T_SEQ + qt * 64 + prow;
#pragma unroll
    for (int nt = 0; nt < 8; nt++) {
        int col = h * HD + nt * 8 + 2 * t;
        float2 v0 = make_float2(oacc[nt][0] * inv0, oacc[nt][1] * inv0);
        float2 v1 = make_float2(oacc[nt][2] * inv1, oacc[nt][3] * inv1);
        *(float2*)&att[(size_t)row * D_MODEL + col] = v0;
        *(float2*)&att[(size_t)(row + 8) * D_MODEL + col] = v1;
    }
}

// ---------------------------------------------------------------------------
// Launch
// ---------------------------------------------------------------------------
extern "C" void kernel_launch(void* const* d_in, const int* in_sizes, int n_in,
                              void* d_out, int out_size)
{
    const float* x      = (const float*)d_in[0];
    const float* bscore = (const float*)d_in[1];
    const float* W_qkv  = (const float*)d_in[2];
    const float* b_qkv  = (const float*)d_in[3];
    const float* W_out  = (const float*)d_in[4];
    const float* b_out  = (const float*)d_in[5];
    float* out = (float*)d_out;

    float* qkv_ptr = nullptr;
    float* att_ptr = nullptr;
    cudaGetSymbolAddress((void**)&qkv_ptr, g_qkv);
    cudaGetSymbolAddress((void**)&att_ptr, g_att);

    (void)cudaFuncSetAttribute(attn_tf32,
        cudaFuncAttributeMaxDynamicSharedMemorySize, ATTN_SMEM_BYTES);

    // 1) QKV projection: [4096,1024] @ [1024,3072] + b
    gemm_tf32_bias<<<dim3(QKV_N / 128, BT / 128), 256>>>(
        x, W_qkv, b_qkv, qkv_ptr, BT, QKV_N, D_MODEL);

    // 2) Flash attention (tf32 MMA)
    attn_tf32<<<dim3(T_SEQ / 64, N_HEADS, BATCH), 128, ATTN_SMEM_BYTES>>>(
        qkv_ptr, bscore, att_ptr);

    // 3) Output projection: [4096,1024] @ [1024,1024] + b
    gemm_tf32_bias<<<dim3(D_MODEL / 128, BT / 128), 256>>>(
        att_ptr, W_out, b_out, out, BT, D_MODEL, D_MODEL);
}

// round 6
// speedup vs baseline: 3.5819x; 1.0806x over previous
#include <cuda_runtime.h>
#include <cuda_bf16.h>
#include <cstdint>

#define BATCH    2
#define T_SEQ    2048
#define D_MODEL  1024
#define N_HEADS  16
#define HD       64
#define BT       (BATCH * T_SEQ)     // 4096
#define QKV_N    (3 * D_MODEL)       // 3072
#define BIAS_COEF 0.1f

// Scratch (device globals: allocation-free per harness rules)
__device__ float g_qkv[(size_t)BT * QKV_N];     // [4096, 3072]  (tf32-rounded)
__device__ float g_att[(size_t)BT * D_MODEL];   // [4096, 1024]  (tf32-rounded)
__device__ float g_xt [(size_t)BT * D_MODEL];   // x rounded
__device__ float g_wq [(size_t)D_MODEL * QKV_N];
__device__ float g_wo [(size_t)D_MODEL * D_MODEL];

// ---------------------------------------------------------------------------
// helpers
// ---------------------------------------------------------------------------
__device__ __forceinline__ uint32_t f2tf32(float f) {
    uint32_t r;
    asm("cvt.rna.tf32.f32 %0, %1;" : "=r"(r) : "f"(f));
    return r;
}
__device__ __forceinline__ float rnd_tf32(float f) {
    return __uint_as_float(f2tf32(f));
}

__device__ __forceinline__ void mma_tf32(float c[4],
    uint32_t a0, uint32_t a1, uint32_t a2, uint32_t a3,
    uint32_t b0, uint32_t b1)
{
    asm volatile(
        "mma.sync.aligned.m16n8k8.row.col.f32.tf32.tf32.f32 "
        "{%0,%1,%2,%3}, {%4,%5,%6,%7}, {%8,%9}, {%0,%1,%2,%3};"
        : "+f"(c[0]), "+f"(c[1]), "+f"(c[2]), "+f"(c[3])
        : "r"(a0), "r"(a1), "r"(a2), "r"(a3), "r"(b0), "r"(b1));
}

__device__ __forceinline__ void cp16(uint32_t saddr, const void* g) {
    asm volatile("cp.async.cg.shared.global [%0], [%1], 16;" :: "r"(saddr), "l"(g));
}
__device__ __forceinline__ void cp_commit() {
    asm volatile("cp.async.commit_group;");
}
__device__ __forceinline__ void cp_wait1() {
    asm volatile("cp.async.wait_group 1;");
}
__device__ __forceinline__ void cp_wait0() {
    asm volatile("cp.async.wait_group 0;");
}
__device__ __forceinline__ uint32_t s2u(const void* p) {
    return (uint32_t)__cvta_generic_to_shared(p);
}

// ---------------------------------------------------------------------------
// Pre-round: out[i] = rna_tf32(in[i]) (vectorized, grid-stride with guard)
// ---------------------------------------------------------------------------
__global__ __launch_bounds__(256) void round_tf32_kernel(
    const float* __restrict__ in, float* __restrict__ out, int n4)
{
    for (int i = blockIdx.x * 256 + threadIdx.x; i < n4; i += gridDim.x * 256) {
        float4 v = *(const float4*)(in + (size_t)i * 4);
        v.x = rnd_tf32(v.x); v.y = rnd_tf32(v.y);
        v.z = rnd_tf32(v.z); v.w = rnd_tf32(v.w);
        *(float4*)(out + (size_t)i * 4) = v;
    }
}

// ---------------------------------------------------------------------------
// TF32 GEMM, cp.async double-buffered. Inputs must be pre-rounded to tf32.
// C = A[MxK] @ B[KxN] + bias.  Block 128x128, BK=32, 2 stages, 8 warps.
// As stride 44 words/row, Bs stride 136 words/row (16B-aligned, conflict-free).
// ---------------------------------------------------------------------------
#define AS_STRIDE 44
#define BS_STRIDE 136
#define AS_STAGE (128 * AS_STRIDE)   // 5632 words
#define BS_STAGE (32 * BS_STRIDE)    // 4352 words
#define GEMM_SMEM_BYTES ((2 * AS_STAGE + 2 * BS_STAGE) * 4)   // 79872

__device__ __forceinline__ void gemm_load_stage(
    const float* __restrict__ Ag, const float* __restrict__ Bg,
    uint32_t* __restrict__ as, uint32_t* __restrict__ bs,
    int k0, int K, int N, int tid)
{
#pragma unroll
    for (int j = 0; j < 4; j++) {
        int i = tid + 256 * j;
        int row = i >> 3, c4 = (i & 7) << 2;
        cp16(s2u(&as[row * AS_STRIDE + c4]), Ag + (size_t)row * K + k0 + c4);
    }
#pragma unroll
    for (int j = 0; j < 4; j++) {
        int i = tid + 256 * j;
        int row = i >> 5, c4 = (i & 31) << 2;
        cp16(s2u(&bs[row * BS_STRIDE + c4]), Bg + (size_t)(k0 + row) * N + c4);
    }
    cp_commit();
}

__global__ __launch_bounds__(256) void gemm_tf32_db(
    const float* __restrict__ A, const float* __restrict__ B,
    const float* __restrict__ bias, float* __restrict__ C,
    int M, int N, int K, int round_out)
{
    extern __shared__ uint32_t smem[];
    uint32_t* As = smem;                    // [2][128*44]
    uint32_t* Bs = smem + 2 * AS_STAGE;     // [2][32*136]

    const int tid  = threadIdx.x;
    const int lane = tid & 31;
    const int warp = tid >> 5;
    const int wr = warp >> 2;
    const int wc = warp & 3;
    const int g = lane >> 2;
    const int t = lane & 3;
    const int bx = blockIdx.x, by = blockIdx.y;

    const float* Ag = A + (size_t)(by * 128) * K;
    const float* Bg = B + bx * 128;
    const int nK = K >> 5;

    float acc[4][4][4];
#pragma unroll
    for (int mt = 0; mt < 4; mt++)
#pragma unroll
        for (int nt = 0; nt < 4; nt++)
#pragma unroll
            for (int i = 0; i < 4; i++) acc[mt][nt][i] = 0.0f;

    gemm_load_stage(Ag, Bg, As, Bs, 0, K, N, tid);

    for (int it = 0; it < nK; it++) {
        int cur = it & 1;
        if (it + 1 < nK) {
            gemm_load_stage(Ag, Bg, As + (cur ^ 1) * AS_STAGE,
                            Bs + (cur ^ 1) * BS_STAGE, (it + 1) << 5, K, N, tid);
            cp_wait1();
        } else {
            cp_wait0();
        }
        __syncthreads();

        const uint32_t* as = As + cur * AS_STAGE;
        const uint32_t* bs = Bs + cur * BS_STAGE;
#pragma unroll
        for (int kk = 0; kk < 4; kk++) {
            uint32_t a[4][4], bf[4][2];
#pragma unroll
            for (int mt = 0; mt < 4; mt++) {
                int r = wr * 64 + mt * 16 + g;
                int c = kk * 8 + t;
                a[mt][0] = as[r * AS_STRIDE + c];
                a[mt][1] = as[(r + 8) * AS_STRIDE + c];
                a[mt][2] = as[r * AS_STRIDE + c + 4];
                a[mt][3] = as[(r + 8) * AS_STRIDE + c + 4];
            }
#pragma unroll
            for (int nt = 0; nt < 4; nt++) {
                int c = wc * 32 + nt * 8 + g;
                int r = kk * 8 + t;
                bf[nt][0] = bs[r * BS_STRIDE + c];
                bf[nt][1] = bs[(r + 4) * BS_STRIDE + c];
            }
#pragma unroll
            for (int mt = 0; mt < 4; mt++)
#pragma unroll
                for (int nt = 0; nt < 4; nt++)
                    mma_tf32(acc[mt][nt], a[mt][0], a[mt][1], a[mt][2], a[mt][3],
                             bf[nt][0], bf[nt][1]);
        }
        __syncthreads();
    }

    // Epilogue: bias + (optional tf32 round) + store
#pragma unroll
    for (int mt = 0; mt < 4; mt++) {
#pragma unroll
        for (int nt = 0; nt < 4; nt++) {
            int row = by * 128 + wr * 64 + mt * 16 + g;
            int col = bx * 128 + wc * 32 + nt * 8 + 2 * t;
            float b0 = bias[col], b1 = bias[col + 1];
            float r00 = acc[mt][nt][0] + b0, r01 = acc[mt][nt][1] + b1;
            float r10 = acc[mt][nt][2] + b0, r11 = acc[mt][nt][3] + b1;
            if (round_out) {
                r00 = rnd_tf32(r00); r01 = rnd_tf32(r01);
                r10 = rnd_tf32(r10); r11 = rnd_tf32(r11);
            }
            *(float2*)&C[(size_t)row * N + col] = make_float2(r00, r01);
            *(float2*)&C[(size_t)(row + 8) * N + col] = make_float2(r10, r11);
        }
    }
}

// ---------------------------------------------------------------------------
// Flash attention, tf32 MMA, cp.async double-buffered K/V/bias.
// Grid (T/64, H, B), 128 threads (4 warps), warp owns 16 q-rows.
// qkv is pre-rounded to tf32 values, so raw bits are valid MMA operands.
// ---------------------------------------------------------------------------
#define KV_STRIDE 68                      // words; 272B, 16B-multiple
#define KV_STAGE  (2 * 64 * KV_STRIDE)    // K + V per stage = 8704 words
#define ATTN_SMEM_U32 (2 * KV_STAGE + 64 * KV_STRIDE + 2 * 64)
#define ATTN_SMEM_BYTES (ATTN_SMEM_U32 * 4)   // ~87.5 KB

__device__ __forceinline__ void attn_prefetch(
    uint32_t* __restrict__ sm_base, float* __restrict__ bias_s,
    const float* __restrict__ kv_base, const float* __restrict__ bs_base,
    int kt, int s, int tid)
{
    uint32_t* Ksb = sm_base + s * KV_STAGE;
    uint32_t* Vsb = Ksb + 64 * KV_STRIDE;
    const float* kb = kv_base + (size_t)(kt * 64) * QKV_N;
    const float* vb = kb + D_MODEL;
#pragma unroll
    for (int j = 0; j < 8; j++) {
        int i = tid + 128 * j;
        int row = i >> 4, c4 = (i & 15) << 2;
        cp16(s2u(&Ksb[row * KV_STRIDE + c4]), kb + (size_t)row * QKV_N + c4);
        cp16(s2u(&Vsb[row * KV_STRIDE + c4]), vb + (size_t)row * QKV_N + c4);
    }
    if (tid < 16)
        cp16(s2u(&bias_s[s * 64 + tid * 4]), bs_base + kt * 64 + tid * 4);
    cp_commit();
}

__global__ __launch_bounds__(128) void attn_tf32(
    const float* __restrict__ qkv, const float* __restrict__ bscore,
    float* __restrict__ att)
{
    extern __shared__ uint32_t sm[];
    uint32_t* Ps = sm + 2 * KV_STAGE;             // [64][68]
    float* bias_s = (float*)(sm + 2 * KV_STAGE + 64 * KV_STRIDE);  // [2][64]

    const int tid  = threadIdx.x;
    const int lane = tid & 31;
    const int w = tid >> 5;
    const int g = lane >> 2;
    const int t = lane & 3;
    const int qt = blockIdx.x, h = blockIdx.y, b = blockIdx.z;

    const float* kv_base = qkv + (size_t)b * T_SEQ * QKV_N + D_MODEL + h * HD;
    const float* bs_base = bscore + b * T_SEQ;

    // Preload Q fragments (pre-rounded values; x0.125 is exact pow2 scale)
    uint32_t qa[8][4];
    {
        const float* q0 = qkv + (size_t)(b * T_SEQ + qt * 64 + w * 16 + g) * QKV_N + h * HD;
        const float* q8 = q0 + 8 * (size_t)QKV_N;
#pragma unroll
        for (int ks = 0; ks < 8; ks++) {
            int c = ks * 8 + t;
            qa[ks][0] = __float_as_uint(q0[c] * 0.125f);
            qa[ks][1] = __float_as_uint(q8[c] * 0.125f);
            qa[ks][2] = __float_as_uint(q0[c + 4] * 0.125f);
            qa[ks][3] = __float_as_uint(q8[c + 4] * 0.125f);
        }
    }

    float oacc[8][4];
#pragma unroll
    for (int nt = 0; nt < 8; nt++)
#pragma unroll
        for (int i = 0; i < 4; i++) oacc[nt][i] = 0.0f;
    float m0 = -1e30f, m1 = -1e30f, l0 = 0.0f, l1 = 0.0f;

    const int prow = w * 16 + g;
    const int NT = T_SEQ / 64;

    attn_prefetch(sm, bias_s, kv_base, bs_base, 0, 0, tid);

    for (int kt = 0; kt < NT; kt++) {
        int cur = kt & 1;
        if (kt + 1 < NT) {
            attn_prefetch(sm, bias_s, kv_base, bs_base, kt + 1, cur ^ 1, tid);
            cp_wait1();
        } else {
            cp_wait0();
        }
        __syncthreads();

        const uint32_t* Ksb = sm + cur * KV_STAGE;
        const uint32_t* Vsb = Ksb + 64 * KV_STRIDE;
        const float* bb = &bias_s[cur * 64];

        // S = Q K^T
        float sacc[8][4];
#pragma unroll
        for (int nt = 0; nt < 8; nt++)
#pragma unroll
            for (int i = 0; i < 4; i++) sacc[nt][i] = 0.0f;
#pragma unroll
        for (int ks = 0; ks < 8; ks++) {
#pragma unroll
            for (int nt = 0; nt < 8; nt++) {
                int key = nt * 8 + g;
                int d = ks * 8 + t;
                uint32_t b0 = Ksb[key * KV_STRIDE + d];
                uint32_t b1 = Ksb[key * KV_STRIDE + d + 4];
                mma_tf32(sacc[nt], qa[ks][0], qa[ks][1], qa[ks][2], qa[ks][3], b0, b1);
            }
        }

        // bias add + tile max
        float mt0 = -1e30f, mt1 = -1e30f;
#pragma unroll
        for (int nt = 0; nt < 8; nt++) {
            float bb0 = bb[nt * 8 + 2 * t] * BIAS_COEF;
            float bb1 = bb[nt * 8 + 2 * t + 1] * BIAS_COEF;
            sacc[nt][0] += bb0; sacc[nt][1] += bb1;
            sacc[nt][2] += bb0; sacc[nt][3] += bb1;
            mt0 = fmaxf(mt0, fmaxf(sacc[nt][0], sacc[nt][1]));
            mt1 = fmaxf(mt1, fmaxf(sacc[nt][2], sacc[nt][3]));
        }
        mt0 = fmaxf(mt0, __shfl_xor_sync(0xFFFFFFFFu, mt0, 1));
        mt0 = fmaxf(mt0, __shfl_xor_sync(0xFFFFFFFFu, mt0, 2));
        mt1 = fmaxf(mt1, __shfl_xor_sync(0xFFFFFFFFu, mt1, 1));
        mt1 = fmaxf(mt1, __shfl_xor_sync(0xFFFFFFFFu, mt1, 2));

        float mn0 = fmaxf(m0, mt0), mn1 = fmaxf(m1, mt1);
        float c0 = __expf(m0 - mn0), c1 = __expf(m1 - mn1);
        m0 = mn0; m1 = mn1;

        float ls0 = 0.0f, ls1 = 0.0f;
#pragma unroll
        for (int nt = 0; nt < 8; nt++) {
            float p0 = __expf(sacc[nt][0] - mn0);
            float p1 = __expf(sacc[nt][1] - mn0);
            float p2 = __expf(sacc[nt][2] - mn1);
            float p3 = __expf(sacc[nt][3] - mn1);
            ls0 += p0 + p1; ls1 += p2 + p3;
            int col = nt * 8 + 2 * t;
            Ps[prow * KV_STRIDE + col] = f2tf32(p0);
            Ps[prow * KV_STRIDE + col + 1] = f2tf32(p1);
            Ps[(prow + 8) * KV_STRIDE + col] = f2tf32(p2);
            Ps[(prow + 8) * KV_STRIDE + col + 1] = f2tf32(p3);
            oacc[nt][0] *= c0; oacc[nt][1] *= c0;
            oacc[nt][2] *= c1; oacc[nt][3] *= c1;
        }
        ls0 += __shfl_xor_sync(0xFFFFFFFFu, ls0, 1);
        ls0 += __shfl_xor_sync(0xFFFFFFFFu, ls0, 2);
        ls1 += __shfl_xor_sync(0xFFFFFFFFu, ls1, 1);
        ls1 += __shfl_xor_sync(0xFFFFFFFFu, ls1, 2);
        l0 = l0 * c0 + ls0;
        l1 = l1 * c1 + ls1;
        __syncwarp(0xFFFFFFFFu);

        // O += P V
#pragma unroll
        for (int ks = 0; ks < 8; ks++) {
            int c = ks * 8 + t;
            uint32_t pa0 = Ps[prow * KV_STRIDE + c];
            uint32_t pa1 = Ps[(prow + 8) * KV_STRIDE + c];
            uint32_t pa2 = Ps[prow * KV_STRIDE + c + 4];
            uint32_t pa3 = Ps[(prow + 8) * KV_STRIDE + c + 4];
#pragma unroll
            for (int nt = 0; nt < 8; nt++) {
                int d = nt * 8 + g;
                int key = ks * 8 + t;
                uint32_t b0 = Vsb[key * KV_STRIDE + d];
                uint32_t b1 = Vsb[(key + 4) * KV_STRIDE + d];
                mma_tf32(oacc[nt], pa0, pa1, pa2, pa3, b0, b1);
            }
        }
        __syncthreads();   // protect buffer 'cur' before next iteration's prefetch
    }

    // Normalize + round + store (pre-rounded for out-proj consumption)
    float inv0 = 1.0f / l0, inv1 = 1.0f / l1;
    int row = b * T_SEQ + qt * 64 + prow;
#pragma unroll
    for (int nt = 0; nt < 8; nt++) {
        int col = h * HD + nt * 8 + 2 * t;
        float2 v0 = make_float2(rnd_tf32(oacc[nt][0] * inv0), rnd_tf32(oacc[nt][1] * inv0));
        float2 v1 = make_float2(rnd_tf32(oacc[nt][2] * inv1), rnd_tf32(oacc[nt][3] * inv1));
        *(float2*)&att[(size_t)row * D_MODEL + col] = v0;
        *(float2*)&att[(size_t)(row + 8) * D_MODEL + col] = v1;
    }
}

// ---------------------------------------------------------------------------
// Launch
// ---------------------------------------------------------------------------
extern "C" void kernel_launch(void* const* d_in, const int* in_sizes, int n_in,
                              void* d_out, int out_size)
{
    const float* x      = (const float*)d_in[0];
    const float* bscore = (const float*)d_in[1];
    const float* W_qkv  = (const float*)d_in[2];
    const float* b_qkv  = (const float*)d_in[3];
    const float* W_out  = (const float*)d_in[4];
    const float* b_out  = (const float*)d_in[5];
    float* out = (float*)d_out;

    float *qkv_p, *att_p, *xt_p, *wq_p, *wo_p;
    cudaGetSymbolAddress((void**)&qkv_p, g_qkv);
    cudaGetSymbolAddress((void**)&att_p, g_att);
    cudaGetSymbolAddress((void**)&xt_p,  g_xt);
    cudaGetSymbolAddress((void**)&wq_p,  g_wq);
    cudaGetSymbolAddress((void**)&wo_p,  g_wo);

    (void)cudaFuncSetAttribute(attn_tf32,
        cudaFuncAttributeMaxDynamicSharedMemorySize, ATTN_SMEM_BYTES);
    (void)cudaFuncSetAttribute(gemm_tf32_db,
        cudaFuncAttributeMaxDynamicSharedMemorySize, GEMM_SMEM_BYTES);

    // 0) Pre-round inputs to tf32 values
    {
        int nx4 = BT * D_MODEL / 4;
        int nq4 = D_MODEL * QKV_N / 4;
        int no4 = D_MODEL * D_MODEL / 4;
        round_tf32_kernel<<<(nx4 + 255) / 256, 256>>>(x, xt_p, nx4);
        round_tf32_kernel<<<(nq4 + 255) / 256, 256>>>(W_qkv, wq_p, nq4);
        round_tf32_kernel<<<(no4 + 255) / 256, 256>>>(W_out, wo_p, no4);
    }

    // 1) QKV projection (round output for attention)
    gemm_tf32_db<<<dim3(QKV_N / 128, BT / 128), 256, GEMM_SMEM_BYTES>>>(
        xt_p, wq_p, b_qkv, qkv_p, BT, QKV_N, D_MODEL, 1);

    // 2) Flash attention
    attn_tf32<<<dim3(T_SEQ / 64, N_HEADS, BATCH), 128, ATTN_SMEM_BYTES>>>(
        qkv_p, bscore, att_p);

    // 3) Output projection (full fp32 output)
    gemm_tf32_db<<<dim3(D_MODEL / 128, BT / 128), 256, GEMM_SMEM_BYTES>>>(
        att_p, wo_p, b_out, out, BT, D_MODEL, D_MODEL, 0);
}